// round 4
// baseline (speedup 1.0000x reference)
#include <cuda_runtime.h>
#include <cstdint>

// HarmonicPolynomialR3Generator — R4: 4 points/thread to halve LDS per point.
//  - 2 f32x2 pairs per thread (points slot, slot+64, slot+128, slot+192 of tile)
//  - 4-way k-split, k-CONTIGUOUS per thread: thread j owns k in [j*TM, j*TM+TM)
//  - cob stored k-major per m (column [m][CS], CS=4*TM, zero padded, dup pairs)
//    -> aligned LDS.128 fetches 2 k-values serving 4 ffma2 (4 points)
//  - m-outer loop: prev[i] loaded once per i (vectorized LDS.128 over i pairs)
//  - staging buffer [256 pts][121 f32] + one cp.async.bulk per CTA
//  - 219KB smem, 256 threads, 1 CTA/SM (8 warps), high per-thread ILP.

typedef unsigned long long ull;

__device__ __forceinline__ ull ffma2(ull a, ull b, ull c) {
    ull d; asm("fma.rn.f32x2 %0, %1, %2, %3;" : "=l"(d) : "l"(a), "l"(b), "l"(c)); return d;
}
__device__ __forceinline__ ull fmul2(ull a, ull b) {
    ull d; asm("mul.rn.f32x2 %0, %1, %2;" : "=l"(d) : "l"(a), "l"(b)); return d;
}
__device__ __forceinline__ ull pack2(float lo, float hi) {
    ull d; asm("mov.b64 %0, {%1, %2};" : "=l"(d) : "f"(lo), "f"(hi)); return d;
}
__device__ __forceinline__ void st2s(float* a, float* b, ull v) {
    float lo, hi; asm("mov.b64 {%0, %1}, %2;" : "=f"(lo), "=f"(hi) : "l"(v));
    *a = lo; *b = hi;
}
__device__ __forceinline__ uint32_t smem_u32(const void* p) {
    uint32_t a;
    asm("{ .reg .u64 t; cvta.to.shared.u64 t, %1; cvt.u32.u64 %0, t; }" : "=r"(a) : "l"(p));
    return a;
}

#define BLOCK 256
#define SLOTS 64
#define TILE  256

// cob smem (ull units): cob1 at 0 (pad 10). Stage l: column-major [3PL][CS],
// column = k-major dup pairs, CS = 4*TM, zero-padded k >= NK.
#define OFF2   10    // PL=3,  TM=2, CS=8,  sz 72
#define OFF3   82    // PL=5,  TM=2, CS=8,  sz 120
#define OFF4   202   // PL=7,  TM=4, CS=16, sz 336
#define OFF5   538   // PL=9,  TM=4, CS=16, sz 432
#define OFF6   970   // PL=11, TM=4, CS=16, sz 528
#define OFF7   1498  // PL=13, TM=4, CS=16, sz 624
#define OFF8   2122  // PL=15, TM=6, CS=24, sz 1080
#define OFF9   3202  // PL=17, TM=6, CS=24, sz 1224
#define OFF10  4426  // PL=19, TM=6, CS=24, sz 1368
#define COB_ULL 5794
#define EX_STRIDE 96              // per-slot: A ping 0, A pong 24, B ping 48, B pong 72
#define EX_ULL (SLOTS * EX_STRIDE)
#define BUF_FLOATS (TILE * 121)
#define SMEM_BYTES ((COB_ULL + EX_ULL) * 8 + BUF_FLOATS * 4)   // 219,408

// Load cob_l (global row-major [NK][3PL]) -> smem [3PL][CS] k-major dup pairs.
template <int PL, int CS>
__device__ __forceinline__ void load_cob(const float* __restrict__ c, ull* __restrict__ dst, int tid) {
    constexpr int NK = PL + 2;
    constexpr int M = 3 * PL;
    for (int e = tid; e < M * CS; e += BLOCK) {
        int m = e / CS;
        int k = e - m * CS;
        float v = (k < NK) ? c[k * M + m] : 0.0f;
        dst[e] = pack2(v, v);
    }
}

// Accumulate contributions of one prev index i (3 m's) into TM accumulators x 2 pairs.
template <int TM, int CS, bool FIRST>
__device__ __forceinline__ void acc_i(const ull* __restrict__ col0, ull pvA, ull pvB,
                                      ull fAx, ull fAy, ull fAz,
                                      ull fBx, ull fBy, ull fBz,
                                      ull* __restrict__ accA, ull* __restrict__ accB) {
#pragma unroll
    for (int c = 0; c < 3; ++c) {
        const ull fA = (c == 0) ? fAx : (c == 1) ? fAy : fAz;
        const ull fB = (c == 0) ? fBx : (c == 1) ? fBy : fBz;
        ull gA = fmul2(pvA, fA);
        ull gB = fmul2(pvB, fB);
        const ull* col = col0 + c * CS;
#pragma unroll
        for (int t2 = 0; t2 < TM / 2; ++t2) {
            ulonglong2 v = *reinterpret_cast<const ulonglong2*>(col + 2 * t2);
            if (FIRST && c == 0) {
                accA[2 * t2]     = fmul2(v.x, gA);
                accA[2 * t2 + 1] = fmul2(v.y, gA);
                accB[2 * t2]     = fmul2(v.x, gB);
                accB[2 * t2 + 1] = fmul2(v.y, gB);
            } else {
                accA[2 * t2]     = ffma2(v.x, gA, accA[2 * t2]);
                accA[2 * t2 + 1] = ffma2(v.y, gA, accA[2 * t2 + 1]);
                accB[2 * t2]     = ffma2(v.x, gB, accB[2 * t2]);
                accB[2 * t2 + 1] = ffma2(v.y, gB, accB[2 * t2 + 1]);
            }
        }
    }
}

// One stage for 4 points (2 pairs). prev read from in*, outputs to out* + buffer.
template <int PL, int TM, int CS>
__device__ __forceinline__ void stage4(const ull* __restrict__ cb, const int j,
                                       ull fAx, ull fAy, ull fAz,
                                       ull fBx, ull fBy, ull fBz,
                                       const ull* __restrict__ inA, const ull* __restrict__ inB,
                                       ull* __restrict__ outA, ull* __restrict__ outB,
                                       float* __restrict__ b0, float* __restrict__ b1,
                                       float* __restrict__ b2, float* __restrict__ b3) {
    constexpr int NK = PL + 2;
    __syncwarp();
    ull accA[TM], accB[TM];
    const ull* cbk = cb + j * TM;

    // i = 0,1 via one aligned 16B exchange load
    {
        ulonglong2 pA = *reinterpret_cast<const ulonglong2*>(inA);
        ulonglong2 pB = *reinterpret_cast<const ulonglong2*>(inB);
        acc_i<TM, CS, true>(cbk, pA.x, pB.x, fAx, fAy, fAz, fBx, fBy, fBz, accA, accB);
        acc_i<TM, CS, false>(cbk + 3 * CS, pA.y, pB.y, fAx, fAy, fAz, fBx, fBy, fBz, accA, accB);
    }
#pragma unroll
    for (int ii = 2; ii + 1 < PL; ii += 2) {
        ulonglong2 pA = *reinterpret_cast<const ulonglong2*>(inA + ii);
        ulonglong2 pB = *reinterpret_cast<const ulonglong2*>(inB + ii);
        acc_i<TM, CS, false>(cbk + 3 * ii * CS, pA.x, pB.x, fAx, fAy, fAz, fBx, fBy, fBz, accA, accB);
        acc_i<TM, CS, false>(cbk + 3 * (ii + 1) * CS, pA.y, pB.y, fAx, fAy, fAz, fBx, fBy, fBz, accA, accB);
    }
    {   // tail i = PL-1 (PL odd)
        ull pvA = inA[PL - 1];
        ull pvB = inB[PL - 1];
        acc_i<TM, CS, false>(cbk + 3 * (PL - 1) * CS, pvA, pvB, fAx, fAy, fAz, fBx, fBy, fBz, accA, accB);
    }
#pragma unroll
    for (int t = 0; t < TM; ++t) {
        const int k = j * TM + t;
        if (k < NK) {
            outA[k] = accA[t];
            outB[k] = accB[t];
            st2s(b0 + k, b1 + k, accA[t]);
            st2s(b2 + k, b3 + k, accB[t]);
        }
    }
}

__global__ void __launch_bounds__(BLOCK, 1)
harmonic_kernel(const float* __restrict__ pts,
                const float* __restrict__ c1, const float* __restrict__ c2,
                const float* __restrict__ c3, const float* __restrict__ c4,
                const float* __restrict__ c5, const float* __restrict__ c6,
                const float* __restrict__ c7, const float* __restrict__ c8,
                const float* __restrict__ c9, const float* __restrict__ c10,
                float* __restrict__ out, int N) {
    extern __shared__ ull dyns[];
    ull* scob = dyns;
    ull* ex = dyns + COB_ULL;
    float* buf = reinterpret_cast<float*>(dyns + COB_ULL + EX_ULL);

    const int tid = threadIdx.x;
    const int slot = tid >> 2;
    const int j = tid & 3;

    if (tid < 9) { float v = c1[tid]; scob[tid] = pack2(v, v); }
    load_cob<3, 8>(c2, scob + OFF2, tid);
    load_cob<5, 8>(c3, scob + OFF3, tid);
    load_cob<7, 16>(c4, scob + OFF4, tid);
    load_cob<9, 16>(c5, scob + OFF5, tid);
    load_cob<11, 16>(c6, scob + OFF6, tid);
    load_cob<13, 16>(c7, scob + OFF7, tid);
    load_cob<15, 24>(c8, scob + OFF8, tid);
    load_cob<17, 24>(c9, scob + OFF9, tid);
    load_cob<19, 24>(c10, scob + OFF10, tid);
    __syncthreads();

    const int base = blockIdx.x * TILE;
    int rem = N - base; if (rem > TILE) rem = TILE;
    const int p0 = base + slot;
    const int p1 = p0 + SLOTS;
    const int p2 = p0 + 2 * SLOTS;
    const int p3 = p0 + 3 * SLOTS;

    float x0 = 0.f, y0 = 0.f, z0 = 0.f, x1 = 0.f, y1 = 0.f, z1 = 0.f;
    float x2 = 0.f, y2 = 0.f, z2 = 0.f, x3 = 0.f, y3 = 0.f, z3 = 0.f;
    if (p0 < N) { x0 = pts[3 * p0]; y0 = pts[3 * p0 + 1]; z0 = pts[3 * p0 + 2]; }
    if (p1 < N) { x1 = pts[3 * p1]; y1 = pts[3 * p1 + 1]; z1 = pts[3 * p1 + 2]; }
    if (p2 < N) { x2 = pts[3 * p2]; y2 = pts[3 * p2 + 1]; z2 = pts[3 * p2 + 2]; }
    if (p3 < N) { x3 = pts[3 * p3]; y3 = pts[3 * p3 + 1]; z3 = pts[3 * p3 + 2]; }
    ull pAx = pack2(x0, x1), pAy = pack2(y0, y1), pAz = pack2(z0, z1);
    ull pBx = pack2(x2, x3), pBy = pack2(y2, y3), pBz = pack2(z2, z3);

    ull fAx = ffma2(scob[0], pAx, ffma2(scob[1], pAy, fmul2(scob[2], pAz)));
    ull fAy = ffma2(scob[3], pAx, ffma2(scob[4], pAy, fmul2(scob[5], pAz)));
    ull fAz = ffma2(scob[6], pAx, ffma2(scob[7], pAy, fmul2(scob[8], pAz)));
    ull fBx = ffma2(scob[0], pBx, ffma2(scob[1], pBy, fmul2(scob[2], pBz)));
    ull fBy = ffma2(scob[3], pBx, ffma2(scob[4], pBy, fmul2(scob[5], pBz)));
    ull fBz = ffma2(scob[6], pBx, ffma2(scob[7], pBy, fmul2(scob[8], pBz)));

    ull* exbase = ex + slot * EX_STRIDE;
    ull* eA0 = exbase;        // pair A ping
    ull* eA1 = exbase + 24;   // pair A pong
    ull* eB0 = exbase + 48;   // pair B ping
    ull* eB1 = exbase + 72;   // pair B pong

    float* b0 = buf + slot * 121;
    float* b1 = b0 + SLOTS * 121;
    float* b2 = b0 + 2 * SLOTS * 121;
    float* b3 = b0 + 3 * SLOTS * 121;

    if (j == 0) {
        b0[0] = 1.0f; b1[0] = 1.0f; b2[0] = 1.0f; b3[0] = 1.0f;
        st2s(b0 + 1, b1 + 1, fAx); st2s(b0 + 2, b1 + 2, fAy); st2s(b0 + 3, b1 + 3, fAz);
        st2s(b2 + 1, b3 + 1, fBx); st2s(b2 + 2, b3 + 2, fBy); st2s(b2 + 3, b3 + 3, fBz);
        eA0[0] = fAx; eA0[1] = fAy; eA0[2] = fAz;
        eB0[0] = fBx; eB0[1] = fBy; eB0[2] = fBz;
    }

    stage4<3, 2, 8>  (scob + OFF2,  j, fAx, fAy, fAz, fBx, fBy, fBz, eA0, eB0, eA1, eB1, b0 + 4,   b1 + 4,   b2 + 4,   b3 + 4);
    stage4<5, 2, 8>  (scob + OFF3,  j, fAx, fAy, fAz, fBx, fBy, fBz, eA1, eB1, eA0, eB0, b0 + 9,   b1 + 9,   b2 + 9,   b3 + 9);
    stage4<7, 4, 16> (scob + OFF4,  j, fAx, fAy, fAz, fBx, fBy, fBz, eA0, eB0, eA1, eB1, b0 + 16,  b1 + 16,  b2 + 16,  b3 + 16);
    stage4<9, 4, 16> (scob + OFF5,  j, fAx, fAy, fAz, fBx, fBy, fBz, eA1, eB1, eA0, eB0, b0 + 25,  b1 + 25,  b2 + 25,  b3 + 25);
    stage4<11, 4, 16>(scob + OFF6,  j, fAx, fAy, fAz, fBx, fBy, fBz, eA0, eB0, eA1, eB1, b0 + 36,  b1 + 36,  b2 + 36,  b3 + 36);
    stage4<13, 4, 16>(scob + OFF7,  j, fAx, fAy, fAz, fBx, fBy, fBz, eA1, eB1, eA0, eB0, b0 + 49,  b1 + 49,  b2 + 49,  b3 + 49);
    stage4<15, 6, 24>(scob + OFF8,  j, fAx, fAy, fAz, fBx, fBy, fBz, eA0, eB0, eA1, eB1, b0 + 64,  b1 + 64,  b2 + 64,  b3 + 64);
    stage4<17, 6, 24>(scob + OFF9,  j, fAx, fAy, fAz, fBx, fBy, fBz, eA1, eB1, eA0, eB0, b0 + 81,  b1 + 81,  b2 + 81,  b3 + 81);
    stage4<19, 6, 24>(scob + OFF10, j, fAx, fAy, fAz, fBx, fBy, fBz, eA0, eB0, eA1, eB1, b0 + 100, b1 + 100, b2 + 100, b3 + 100);

    __syncthreads();
    asm volatile("fence.proxy.async.shared::cta;" ::: "memory");

    const unsigned bytes = (unsigned)rem * 121u * 4u;
    const unsigned mainb = bytes & ~15u;
    float* gdst = out + (size_t)base * 121;
    if (tid == 0 && mainb) {
        uint32_t saddr = smem_u32(buf);
        asm volatile("cp.async.bulk.global.shared::cta.bulk_group [%0], [%1], %2;"
                     :: "l"(gdst), "r"(saddr), "r"(mainb) : "memory");
        asm volatile("cp.async.bulk.commit_group;" ::: "memory");
    }
    for (int e = (int)(mainb >> 2) + tid; e < rem * 121; e += BLOCK)
        gdst[e] = buf[e];
    if (tid == 0 && mainb)
        asm volatile("cp.async.bulk.wait_group 0;" ::: "memory");
}

extern "C" void kernel_launch(void* const* d_in, const int* in_sizes, int n_in,
                              void* d_out, int out_size) {
    const float* points = (const float*)d_in[0];
    const int N = in_sizes[0] / 3;
    float* out = (float*)d_out;

    cudaFuncSetAttribute(harmonic_kernel,
                         cudaFuncAttributeMaxDynamicSharedMemorySize, SMEM_BYTES);

    const int grid = (N + TILE - 1) / TILE;
    harmonic_kernel<<<grid, BLOCK, SMEM_BYTES>>>(
        points,
        (const float*)d_in[1], (const float*)d_in[2], (const float*)d_in[3],
        (const float*)d_in[4], (const float*)d_in[5], (const float*)d_in[6],
        (const float*)d_in[7], (const float*)d_in[8], (const float*)d_in[9],
        (const float*)d_in[10],
        out, N);
}

// round 5
// speedup vs baseline: 1.2974x; 1.2974x over previous
#include <cuda_runtime.h>
#include <cstdint>

// HarmonicPolynomialR3Generator — R5: un-duplicated cob (f32) + in-register
// pair packing. LDS wavefront cost of cob halves vs R4.
//  - 4 points/thread as 2 f32x2 pairs; 4-way k-split (thread j owns k in
//    [j*TM, j*TM+TM)); cob stored k-major f32 columns, float4/float2 loads,
//    each value packed to (v,v) once via mov.b64 and reused for both pairs.
//  - exchange of prev through per-slot smem ping-pong (packed ull), __syncwarp.
//  - staging buffer [128 pts][121 f32] + one cp.async.bulk per CTA.
//  - 112.6KB smem, 128 thr/CTA, 2 CTAs/SM -> 8 warps/SM.

typedef unsigned long long ull;

__device__ __forceinline__ ull ffma2(ull a, ull b, ull c) {
    ull d; asm("fma.rn.f32x2 %0, %1, %2, %3;" : "=l"(d) : "l"(a), "l"(b), "l"(c)); return d;
}
__device__ __forceinline__ ull fmul2(ull a, ull b) {
    ull d; asm("mul.rn.f32x2 %0, %1, %2;" : "=l"(d) : "l"(a), "l"(b)); return d;
}
__device__ __forceinline__ ull pack2(float lo, float hi) {
    ull d; asm("mov.b64 %0, {%1, %2};" : "=l"(d) : "f"(lo), "f"(hi)); return d;
}
__device__ __forceinline__ void st2s(float* a, float* b, ull v) {
    float lo, hi; asm("mov.b64 {%0, %1}, %2;" : "=f"(lo), "=f"(hi) : "l"(v));
    *a = lo; *b = hi;
}
__device__ __forceinline__ uint32_t smem_u32(const void* p) {
    uint32_t a;
    asm("{ .reg .u64 t; cvta.to.shared.u64 t, %1; cvt.u32.u64 %0, t; }" : "=r"(a) : "l"(p));
    return a;
}

#define BLOCK 128
#define SLOTS 32
#define TILE  128

// cob smem (float units). Stage l: [3PL][CS] f32, k-major within per-j slot of
// width SLOTW (CS = 4*SLOTW), zero padded. Offsets in floats (16B aligned).
#define OFF2   16    // PL=3,  TM=2, SLOTW=2, CS=8,  sz 72
#define OFF3   88    // PL=5,  TM=2, SLOTW=2, CS=8,  sz 120
#define OFF4   208   // PL=7,  TM=4, SLOTW=4, CS=16, sz 336
#define OFF5   544   // PL=9,  TM=4, SLOTW=4, CS=16, sz 432
#define OFF6   976   // PL=11, TM=4, SLOTW=4, CS=16, sz 528
#define OFF7   1504  // PL=13, TM=4, SLOTW=4, CS=16, sz 624
#define OFF8   2128  // PL=15, TM=6, SLOTW=8, CS=32, sz 1440
#define OFF9   3568  // PL=17, TM=6, SLOTW=8, CS=32, sz 1632
#define OFF10  5200  // PL=19, TM=6, SLOTW=8, CS=32, sz 1824
#define COB_F  7024
#define EX_STRIDE 88              // per-slot ull: A ping 0, A pong 22, B ping 44, B pong 66
#define EX_ULL (SLOTS * EX_STRIDE)
#define BUF_FLOATS (TILE * 121)
#define SMEM_BYTES (COB_F * 4 + EX_ULL * 8 + BUF_FLOATS * 4)   // 112576

// Load cob_l (global row-major [NK][3PL]) -> smem [3PL][CS] f32 k-major slots.
template <int PL, int TM, int SLOTW>
__device__ __forceinline__ void load_cob(const float* __restrict__ c, float* __restrict__ dst, int tid) {
    constexpr int NK = PL + 2;
    constexpr int M = 3 * PL;
    constexpr int CS = 4 * SLOTW;
    for (int e = tid; e < M * CS; e += BLOCK) {
        int m = e / CS;
        int r = e - m * CS;
        int jj = r / SLOTW;
        int t = r - jj * SLOTW;
        int k = jj * TM + t;
        float v = (t < TM && k < NK) ? c[k * M + m] : 0.0f;
        dst[e] = v;
    }
}

// Accumulate one prev index i (3 m's) into TM accumulators for both pairs.
template <int TM, int CS, bool FIRST>
__device__ __forceinline__ void acc_i(const float* __restrict__ col0, ull pvA, ull pvB,
                                      ull fAx, ull fAy, ull fAz,
                                      ull fBx, ull fBy, ull fBz,
                                      ull* __restrict__ accA, ull* __restrict__ accB) {
#pragma unroll
    for (int c = 0; c < 3; ++c) {
        const ull fA = (c == 0) ? fAx : (c == 1) ? fAy : fAz;
        const ull fB = (c == 0) ? fBx : (c == 1) ? fBy : fBz;
        ull gA = fmul2(pvA, fA);
        ull gB = fmul2(pvB, fB);
        const float* col = col0 + c * CS;
        ull pk[TM];
        if constexpr (TM == 2) {
            float2 v = *reinterpret_cast<const float2*>(col);
            pk[0] = pack2(v.x, v.x); pk[1] = pack2(v.y, v.y);
        } else if constexpr (TM == 4) {
            float4 v = *reinterpret_cast<const float4*>(col);
            pk[0] = pack2(v.x, v.x); pk[1] = pack2(v.y, v.y);
            pk[2] = pack2(v.z, v.z); pk[3] = pack2(v.w, v.w);
        } else {
            float4 v = *reinterpret_cast<const float4*>(col);
            float2 w = *reinterpret_cast<const float2*>(col + 4);
            pk[0] = pack2(v.x, v.x); pk[1] = pack2(v.y, v.y);
            pk[2] = pack2(v.z, v.z); pk[3] = pack2(v.w, v.w);
            pk[4] = pack2(w.x, w.x); pk[5] = pack2(w.y, w.y);
        }
#pragma unroll
        for (int t = 0; t < TM; ++t) {
            if (FIRST && c == 0) {
                accA[t] = fmul2(pk[t], gA);
                accB[t] = fmul2(pk[t], gB);
            } else {
                accA[t] = ffma2(pk[t], gA, accA[t]);
                accB[t] = ffma2(pk[t], gB, accB[t]);
            }
        }
    }
}

// One stage for 4 points (2 pairs).
template <int PL, int TM, int SLOTW>
__device__ __forceinline__ void stage5(const float* __restrict__ cb, const int j,
                                       ull fAx, ull fAy, ull fAz,
                                       ull fBx, ull fBy, ull fBz,
                                       const ull* __restrict__ inA, const ull* __restrict__ inB,
                                       ull* __restrict__ outA, ull* __restrict__ outB,
                                       float* __restrict__ b0, float* __restrict__ b1,
                                       float* __restrict__ b2, float* __restrict__ b3) {
    constexpr int NK = PL + 2;
    constexpr int CS = 4 * SLOTW;
    __syncwarp();
    ull accA[TM], accB[TM];
    const float* cbj = cb + j * SLOTW;

    {   // i = 0,1 via one aligned 16B exchange load
        ulonglong2 pA = *reinterpret_cast<const ulonglong2*>(inA);
        ulonglong2 pB = *reinterpret_cast<const ulonglong2*>(inB);
        acc_i<TM, CS, true>(cbj, pA.x, pB.x, fAx, fAy, fAz, fBx, fBy, fBz, accA, accB);
        acc_i<TM, CS, false>(cbj + 3 * CS, pA.y, pB.y, fAx, fAy, fAz, fBx, fBy, fBz, accA, accB);
    }
#pragma unroll
    for (int ii = 2; ii + 1 < PL; ii += 2) {
        ulonglong2 pA = *reinterpret_cast<const ulonglong2*>(inA + ii);
        ulonglong2 pB = *reinterpret_cast<const ulonglong2*>(inB + ii);
        acc_i<TM, CS, false>(cbj + 3 * ii * CS, pA.x, pB.x, fAx, fAy, fAz, fBx, fBy, fBz, accA, accB);
        acc_i<TM, CS, false>(cbj + 3 * (ii + 1) * CS, pA.y, pB.y, fAx, fAy, fAz, fBx, fBy, fBz, accA, accB);
    }
    {   // tail i = PL-1 (PL odd)
        ull pvA = inA[PL - 1];
        ull pvB = inB[PL - 1];
        acc_i<TM, CS, false>(cbj + 3 * (PL - 1) * CS, pvA, pvB, fAx, fAy, fAz, fBx, fBy, fBz, accA, accB);
    }
#pragma unroll
    for (int t = 0; t < TM; ++t) {
        const int k = j * TM + t;
        if (k < NK) {
            outA[k] = accA[t];
            outB[k] = accB[t];
            st2s(b0 + k, b1 + k, accA[t]);
            st2s(b2 + k, b3 + k, accB[t]);
        }
    }
}

__global__ void __launch_bounds__(BLOCK, 2)
harmonic_kernel(const float* __restrict__ pts,
                const float* __restrict__ c1, const float* __restrict__ c2,
                const float* __restrict__ c3, const float* __restrict__ c4,
                const float* __restrict__ c5, const float* __restrict__ c6,
                const float* __restrict__ c7, const float* __restrict__ c8,
                const float* __restrict__ c9, const float* __restrict__ c10,
                float* __restrict__ out, int N) {
    extern __shared__ float dynf[];
    float* scob = dynf;
    ull* ex = reinterpret_cast<ull*>(dynf + COB_F);
    float* buf = dynf + COB_F + EX_ULL * 2;

    const int tid = threadIdx.x;
    const int slot = tid >> 2;
    const int j = tid & 3;

    if (tid < 16) scob[tid] = (tid < 9) ? c1[tid] : 0.0f;
    load_cob<3, 2, 2>(c2, scob + OFF2, tid);
    load_cob<5, 2, 2>(c3, scob + OFF3, tid);
    load_cob<7, 4, 4>(c4, scob + OFF4, tid);
    load_cob<9, 4, 4>(c5, scob + OFF5, tid);
    load_cob<11, 4, 4>(c6, scob + OFF6, tid);
    load_cob<13, 4, 4>(c7, scob + OFF7, tid);
    load_cob<15, 6, 8>(c8, scob + OFF8, tid);
    load_cob<17, 6, 8>(c9, scob + OFF9, tid);
    load_cob<19, 6, 8>(c10, scob + OFF10, tid);
    __syncthreads();

    const int base = blockIdx.x * TILE;
    int rem = N - base; if (rem > TILE) rem = TILE;
    const int p0 = base + slot;
    const int p1 = p0 + SLOTS;
    const int p2 = p0 + 2 * SLOTS;
    const int p3 = p0 + 3 * SLOTS;

    float x0 = 0.f, y0 = 0.f, z0 = 0.f, x1 = 0.f, y1 = 0.f, z1 = 0.f;
    float x2 = 0.f, y2 = 0.f, z2 = 0.f, x3 = 0.f, y3 = 0.f, z3 = 0.f;
    if (p0 < N) { x0 = pts[3 * p0]; y0 = pts[3 * p0 + 1]; z0 = pts[3 * p0 + 2]; }
    if (p1 < N) { x1 = pts[3 * p1]; y1 = pts[3 * p1 + 1]; z1 = pts[3 * p1 + 2]; }
    if (p2 < N) { x2 = pts[3 * p2]; y2 = pts[3 * p2 + 1]; z2 = pts[3 * p2 + 2]; }
    if (p3 < N) { x3 = pts[3 * p3]; y3 = pts[3 * p3 + 1]; z3 = pts[3 * p3 + 2]; }
    ull pAx = pack2(x0, x1), pAy = pack2(y0, y1), pAz = pack2(z0, z1);
    ull pBx = pack2(x2, x3), pBy = pack2(y2, y3), pBz = pack2(z2, z3);

    ull k0 = pack2(scob[0], scob[0]), k1 = pack2(scob[1], scob[1]), k2 = pack2(scob[2], scob[2]);
    ull k3 = pack2(scob[3], scob[3]), k4 = pack2(scob[4], scob[4]), k5 = pack2(scob[5], scob[5]);
    ull k6 = pack2(scob[6], scob[6]), k7 = pack2(scob[7], scob[7]), k8 = pack2(scob[8], scob[8]);

    ull fAx = ffma2(k0, pAx, ffma2(k1, pAy, fmul2(k2, pAz)));
    ull fAy = ffma2(k3, pAx, ffma2(k4, pAy, fmul2(k5, pAz)));
    ull fAz = ffma2(k6, pAx, ffma2(k7, pAy, fmul2(k8, pAz)));
    ull fBx = ffma2(k0, pBx, ffma2(k1, pBy, fmul2(k2, pBz)));
    ull fBy = ffma2(k3, pBx, ffma2(k4, pBy, fmul2(k5, pBz)));
    ull fBz = ffma2(k6, pBx, ffma2(k7, pBy, fmul2(k8, pBz)));

    ull* exbase = ex + slot * EX_STRIDE;
    ull* eA0 = exbase;        // pair A ping
    ull* eA1 = exbase + 22;   // pair A pong
    ull* eB0 = exbase + 44;   // pair B ping
    ull* eB1 = exbase + 66;   // pair B pong

    float* b0 = buf + slot * 121;
    float* b1 = b0 + SLOTS * 121;
    float* b2 = b0 + 2 * SLOTS * 121;
    float* b3 = b0 + 3 * SLOTS * 121;

    if (j == 0) {
        b0[0] = 1.0f; b1[0] = 1.0f; b2[0] = 1.0f; b3[0] = 1.0f;
        st2s(b0 + 1, b1 + 1, fAx); st2s(b0 + 2, b1 + 2, fAy); st2s(b0 + 3, b1 + 3, fAz);
        st2s(b2 + 1, b3 + 1, fBx); st2s(b2 + 2, b3 + 2, fBy); st2s(b2 + 3, b3 + 3, fBz);
        eA0[0] = fAx; eA0[1] = fAy; eA0[2] = fAz;
        eB0[0] = fBx; eB0[1] = fBy; eB0[2] = fBz;
    }

    stage5<3, 2, 2>  (scob + OFF2,  j, fAx, fAy, fAz, fBx, fBy, fBz, eA0, eB0, eA1, eB1, b0 + 4,   b1 + 4,   b2 + 4,   b3 + 4);
    stage5<5, 2, 2>  (scob + OFF3,  j, fAx, fAy, fAz, fBx, fBy, fBz, eA1, eB1, eA0, eB0, b0 + 9,   b1 + 9,   b2 + 9,   b3 + 9);
    stage5<7, 4, 4>  (scob + OFF4,  j, fAx, fAy, fAz, fBx, fBy, fBz, eA0, eB0, eA1, eB1, b0 + 16,  b1 + 16,  b2 + 16,  b3 + 16);
    stage5<9, 4, 4>  (scob + OFF5,  j, fAx, fAy, fAz, fBx, fBy, fBz, eA1, eB1, eA0, eB0, b0 + 25,  b1 + 25,  b2 + 25,  b3 + 25);
    stage5<11, 4, 4> (scob + OFF6,  j, fAx, fAy, fAz, fBx, fBy, fBz, eA0, eB0, eA1, eB1, b0 + 36,  b1 + 36,  b2 + 36,  b3 + 36);
    stage5<13, 4, 4> (scob + OFF7,  j, fAx, fAy, fAz, fBx, fBy, fBz, eA1, eB1, eA0, eB0, b0 + 49,  b1 + 49,  b2 + 49,  b3 + 49);
    stage5<15, 6, 8> (scob + OFF8,  j, fAx, fAy, fAz, fBx, fBy, fBz, eA0, eB0, eA1, eB1, b0 + 64,  b1 + 64,  b2 + 64,  b3 + 64);
    stage5<17, 6, 8> (scob + OFF9,  j, fAx, fAy, fAz, fBx, fBy, fBz, eA1, eB1, eA0, eB0, b0 + 81,  b1 + 81,  b2 + 81,  b3 + 81);
    stage5<19, 6, 8> (scob + OFF10, j, fAx, fAy, fAz, fBx, fBy, fBz, eA0, eB0, eA1, eB1, b0 + 100, b1 + 100, b2 + 100, b3 + 100);

    __syncthreads();
    asm volatile("fence.proxy.async.shared::cta;" ::: "memory");

    const unsigned bytes = (unsigned)rem * 121u * 4u;
    const unsigned mainb = bytes & ~15u;
    float* gdst = out + (size_t)base * 121;
    if (tid == 0 && mainb) {
        uint32_t saddr = smem_u32(buf);
        asm volatile("cp.async.bulk.global.shared::cta.bulk_group [%0], [%1], %2;"
                     :: "l"(gdst), "r"(saddr), "r"(mainb) : "memory");
        asm volatile("cp.async.bulk.commit_group;" ::: "memory");
    }
    for (int e = (int)(mainb >> 2) + tid; e < rem * 121; e += BLOCK)
        gdst[e] = buf[e];
    if (tid == 0 && mainb)
        asm volatile("cp.async.bulk.wait_group 0;" ::: "memory");
}

extern "C" void kernel_launch(void* const* d_in, const int* in_sizes, int n_in,
                              void* d_out, int out_size) {
    const float* points = (const float*)d_in[0];
    const int N = in_sizes[0] / 3;
    float* out = (float*)d_out;

    cudaFuncSetAttribute(harmonic_kernel,
                         cudaFuncAttributeMaxDynamicSharedMemorySize, SMEM_BYTES);

    const int grid = (N + TILE - 1) / TILE;
    harmonic_kernel<<<grid, BLOCK, SMEM_BYTES>>>(
        points,
        (const float*)d_in[1], (const float*)d_in[2], (const float*)d_in[3],
        (const float*)d_in[4], (const float*)d_in[5], (const float*)d_in[6],
        (const float*)d_in[7], (const float*)d_in[8], (const float*)d_in[9],
        (const float*)d_in[10],
        out, N);
}

// round 6
// speedup vs baseline: 1.4887x; 1.1474x over previous
#include <cuda_runtime.h>
#include <cstdint>

// HarmonicPolynomialR3Generator — R6: no staging buffer; per-stage coalesced
// copy straight from the exchange array; conflict-free exchange strides.
//  - 4 points/thread (2 f32x2 pairs: slot, +32, +64, +96), 4-way k-split.
//  - cob f32 k-major slots (R5 layout), packed to (v,v) in registers.
//  - exchange per slot: stride 94 ull (slot offsets cover all 32 banks) with
//    phase0 A/B at 0/22, phase1 A/B at 44/66, f1 header at 88/91.
//  - pipeline: [copy stage l || compute stage l+1] per __syncthreads window.
//  - smem 52.2 KB -> 4 CTAs/SM = 16 warps (2x R5).

typedef unsigned long long ull;

__device__ __forceinline__ ull ffma2(ull a, ull b, ull c) {
    ull d; asm("fma.rn.f32x2 %0, %1, %2, %3;" : "=l"(d) : "l"(a), "l"(b), "l"(c)); return d;
}
__device__ __forceinline__ ull fmul2(ull a, ull b) {
    ull d; asm("mul.rn.f32x2 %0, %1, %2;" : "=l"(d) : "l"(a), "l"(b)); return d;
}
__device__ __forceinline__ ull pack2(float lo, float hi) {
    ull d; asm("mov.b64 %0, {%1, %2};" : "=l"(d) : "f"(lo), "f"(hi)); return d;
}

#define BLOCK 128
#define SLOTS 32
#define TILE  128

// cob smem (float units), R5 layout: [3PL][CS] k-major per-j slots.
#define OFF2   16    // PL=3,  TM=2, SLOTW=2, CS=8
#define OFF3   88    // PL=5,  TM=2, SLOTW=2, CS=8
#define OFF4   208   // PL=7,  TM=4, SLOTW=4, CS=16
#define OFF5   544   // PL=9,  TM=4, SLOTW=4, CS=16
#define OFF6   976   // PL=11, TM=4, SLOTW=4, CS=16
#define OFF7   1504  // PL=13, TM=4, SLOTW=4, CS=16
#define OFF8   2128  // PL=15, TM=6, SLOTW=8, CS=32
#define OFF9   3568  // PL=17, TM=6, SLOTW=8, CS=32
#define OFF10  5200  // PL=19, TM=6, SLOTW=8, CS=32
#define COB_F  7024

#define EXS    94                 // ull per slot: 2*94 mod 32 = 28 -> all-bank spread
#define PH0_A  0
#define PH0_B  22
#define PH1_A  44
#define PH1_B  66
#define HDR_A  88
#define HDR_B  91
#define EX_ULL (SLOTS * EXS)
#define SMEM_BYTES (COB_F * 4 + EX_ULL * 8)   // 28096 + 24064 = 52160

template <int PL, int TM, int SLOTW>
__device__ __forceinline__ void load_cob(const float* __restrict__ c, float* __restrict__ dst, int tid) {
    constexpr int NK = PL + 2;
    constexpr int M = 3 * PL;
    constexpr int CS = 4 * SLOTW;
    for (int e = tid; e < M * CS; e += BLOCK) {
        int m = e / CS;
        int r = e - m * CS;
        int jj = r / SLOTW;
        int t = r - jj * SLOTW;
        int k = jj * TM + t;
        dst[e] = (t < TM && k < NK) ? c[k * M + m] : 0.0f;
    }
}

// Accumulate one prev index i (3 m's) into TM accumulators for both pairs.
template <int TM, int CS, bool FIRST>
__device__ __forceinline__ void acc_i(const float* __restrict__ col0, ull pvA, ull pvB,
                                      ull fAx, ull fAy, ull fAz,
                                      ull fBx, ull fBy, ull fBz,
                                      ull* __restrict__ accA, ull* __restrict__ accB) {
#pragma unroll
    for (int c = 0; c < 3; ++c) {
        const ull fA = (c == 0) ? fAx : (c == 1) ? fAy : fAz;
        const ull fB = (c == 0) ? fBx : (c == 1) ? fBy : fBz;
        ull gA = fmul2(pvA, fA);
        ull gB = fmul2(pvB, fB);
        const float* col = col0 + c * CS;
        ull pk[TM];
        if constexpr (TM == 2) {
            float2 v = *reinterpret_cast<const float2*>(col);
            pk[0] = pack2(v.x, v.x); pk[1] = pack2(v.y, v.y);
        } else if constexpr (TM == 4) {
            float4 v = *reinterpret_cast<const float4*>(col);
            pk[0] = pack2(v.x, v.x); pk[1] = pack2(v.y, v.y);
            pk[2] = pack2(v.z, v.z); pk[3] = pack2(v.w, v.w);
        } else {
            float4 v = *reinterpret_cast<const float4*>(col);
            float2 w = *reinterpret_cast<const float2*>(col + 4);
            pk[0] = pack2(v.x, v.x); pk[1] = pack2(v.y, v.y);
            pk[2] = pack2(v.z, v.z); pk[3] = pack2(v.w, v.w);
            pk[4] = pack2(w.x, w.x); pk[5] = pack2(w.y, w.y);
        }
#pragma unroll
        for (int t = 0; t < TM; ++t) {
            if (FIRST && c == 0) {
                accA[t] = fmul2(pk[t], gA);
                accB[t] = fmul2(pk[t], gB);
            } else {
                accA[t] = ffma2(pk[t], gA, accA[t]);
                accB[t] = ffma2(pk[t], gB, accB[t]);
            }
        }
    }
}

// Generic stage (l >= 3): prev read from exchange, outputs to exchange only.
template <int PL, int TM, int SLOTW>
__device__ __forceinline__ void stage6(const float* __restrict__ cb, const int j,
                                       ull fAx, ull fAy, ull fAz,
                                       ull fBx, ull fBy, ull fBz,
                                       const ull* __restrict__ inA, const ull* __restrict__ inB,
                                       ull* __restrict__ outA, ull* __restrict__ outB) {
    constexpr int NK = PL + 2;
    constexpr int CS = 4 * SLOTW;
    ull accA[TM], accB[TM];
    const float* cbj = cb + j * SLOTW;

    {   // i = 0,1 via one aligned 16B exchange load
        ulonglong2 pA = *reinterpret_cast<const ulonglong2*>(inA);
        ulonglong2 pB = *reinterpret_cast<const ulonglong2*>(inB);
        acc_i<TM, CS, true>(cbj, pA.x, pB.x, fAx, fAy, fAz, fBx, fBy, fBz, accA, accB);
        acc_i<TM, CS, false>(cbj + 3 * CS, pA.y, pB.y, fAx, fAy, fAz, fBx, fBy, fBz, accA, accB);
    }
#pragma unroll
    for (int ii = 2; ii + 1 < PL; ii += 2) {
        ulonglong2 pA = *reinterpret_cast<const ulonglong2*>(inA + ii);
        ulonglong2 pB = *reinterpret_cast<const ulonglong2*>(inB + ii);
        acc_i<TM, CS, false>(cbj + 3 * ii * CS, pA.x, pB.x, fAx, fAy, fAz, fBx, fBy, fBz, accA, accB);
        acc_i<TM, CS, false>(cbj + 3 * (ii + 1) * CS, pA.y, pB.y, fAx, fAy, fAz, fBx, fBy, fBz, accA, accB);
    }
    {   // tail i = PL-1 (PL odd)
        acc_i<TM, CS, false>(cbj + 3 * (PL - 1) * CS, inA[PL - 1], inB[PL - 1],
                             fAx, fAy, fAz, fBx, fBy, fBz, accA, accB);
    }
#pragma unroll
    for (int t = 0; t < TM; ++t) {
        const int k = j * TM + t;
        if (k < NK) { outA[k] = accA[t]; outB[k] = accB[t]; }
    }
}

// Coalesced copy of one stage's outputs from exchange to gmem.
template <int NK, int OUTOFF, int POFF>
__device__ __forceinline__ void copy_stage(const float* __restrict__ exf,
                                           float* __restrict__ out,
                                           int base, int rem, int tid) {
#pragma unroll
    for (int i = 0; i < NK; ++i) {
        int e = tid + i * BLOCK;
        int pt = e / NK;
        int k = e - pt * NK;
        if (pt < rem) {
            int slot = pt & 31;
            int g = pt >> 5;
            int uoff = slot * EXS + POFF + ((g & 2) ? 22 : 0) + k;
            float v = exf[2 * uoff + (g & 1)];
            __stcs(out + (size_t)(base + pt) * 121 + OUTOFF + k, v);
        }
    }
}

__device__ __forceinline__ void copy_hdr(const float* __restrict__ exf,
                                         float* __restrict__ out,
                                         int base, int rem, int tid) {
#pragma unroll
    for (int i = 0; i < 4; ++i) {
        int e = tid + i * BLOCK;
        int pt = e >> 2;
        int k = e & 3;
        if (pt < rem) {
            int slot = pt & 31;
            int g = pt >> 5;
            float v = 1.0f;
            if (k != 0)
                v = exf[2 * (slot * EXS + ((g & 2) ? HDR_B : HDR_A) + (k - 1)) + (g & 1)];
            __stcs(out + (size_t)(base + pt) * 121 + k, v);
        }
    }
}

__global__ void __launch_bounds__(BLOCK, 4)
harmonic_kernel(const float* __restrict__ pts,
                const float* __restrict__ c1, const float* __restrict__ c2,
                const float* __restrict__ c3, const float* __restrict__ c4,
                const float* __restrict__ c5, const float* __restrict__ c6,
                const float* __restrict__ c7, const float* __restrict__ c8,
                const float* __restrict__ c9, const float* __restrict__ c10,
                float* __restrict__ out, int N) {
    extern __shared__ float dynf[];
    float* scob = dynf;
    ull* ex = reinterpret_cast<ull*>(dynf + COB_F);
    float* exf = dynf + COB_F;

    const int tid = threadIdx.x;
    const int slot = tid >> 2;
    const int j = tid & 3;

    if (tid < 16) scob[tid] = (tid < 9) ? c1[tid] : 0.0f;
    load_cob<3, 2, 2>(c2, scob + OFF2, tid);
    load_cob<5, 2, 2>(c3, scob + OFF3, tid);
    load_cob<7, 4, 4>(c4, scob + OFF4, tid);
    load_cob<9, 4, 4>(c5, scob + OFF5, tid);
    load_cob<11, 4, 4>(c6, scob + OFF6, tid);
    load_cob<13, 4, 4>(c7, scob + OFF7, tid);
    load_cob<15, 6, 8>(c8, scob + OFF8, tid);
    load_cob<17, 6, 8>(c9, scob + OFF9, tid);
    load_cob<19, 6, 8>(c10, scob + OFF10, tid);
    __syncthreads();

    const int base = blockIdx.x * TILE;
    int rem = N - base; if (rem > TILE) rem = TILE;
    const int p0 = base + slot;
    const int p1 = p0 + SLOTS;
    const int p2 = p0 + 2 * SLOTS;
    const int p3 = p0 + 3 * SLOTS;

    float x0 = 0.f, y0 = 0.f, z0 = 0.f, x1 = 0.f, y1 = 0.f, z1 = 0.f;
    float x2 = 0.f, y2 = 0.f, z2 = 0.f, x3 = 0.f, y3 = 0.f, z3 = 0.f;
    if (p0 < N) { x0 = pts[3 * p0]; y0 = pts[3 * p0 + 1]; z0 = pts[3 * p0 + 2]; }
    if (p1 < N) { x1 = pts[3 * p1]; y1 = pts[3 * p1 + 1]; z1 = pts[3 * p1 + 2]; }
    if (p2 < N) { x2 = pts[3 * p2]; y2 = pts[3 * p2 + 1]; z2 = pts[3 * p2 + 2]; }
    if (p3 < N) { x3 = pts[3 * p3]; y3 = pts[3 * p3 + 1]; z3 = pts[3 * p3 + 2]; }
    ull pAx = pack2(x0, x1), pAy = pack2(y0, y1), pAz = pack2(z0, z1);
    ull pBx = pack2(x2, x3), pBy = pack2(y2, y3), pBz = pack2(z2, z3);

    ull k0 = pack2(scob[0], scob[0]), k1 = pack2(scob[1], scob[1]), k2 = pack2(scob[2], scob[2]);
    ull k3 = pack2(scob[3], scob[3]), k4 = pack2(scob[4], scob[4]), k5 = pack2(scob[5], scob[5]);
    ull k6 = pack2(scob[6], scob[6]), k7 = pack2(scob[7], scob[7]), k8 = pack2(scob[8], scob[8]);

    ull fAx = ffma2(k0, pAx, ffma2(k1, pAy, fmul2(k2, pAz)));
    ull fAy = ffma2(k3, pAx, ffma2(k4, pAy, fmul2(k5, pAz)));
    ull fAz = ffma2(k6, pAx, ffma2(k7, pAy, fmul2(k8, pAz)));
    ull fBx = ffma2(k0, pBx, ffma2(k1, pBy, fmul2(k2, pBz)));
    ull fBy = ffma2(k3, pBx, ffma2(k4, pBy, fmul2(k5, pBz)));
    ull fBz = ffma2(k6, pBx, ffma2(k7, pBy, fmul2(k8, pBz)));

    ull* es = ex + slot * EXS;
    if (j == 0) {
        es[HDR_A] = fAx; es[HDR_A + 1] = fAy; es[HDR_A + 2] = fAz;
        es[HDR_B] = fBx; es[HDR_B + 1] = fBy; es[HDR_B + 2] = fBz;
    }

    // ---- stage l=2 (prev = f1 in registers) -> phase0 ----
    {
        ull accA[2], accB[2];
        const float* cbj = scob + OFF2 + j * 2;
        acc_i<2, 8, true >(cbj,          fAx, fBx, fAx, fAy, fAz, fBx, fBy, fBz, accA, accB);
        acc_i<2, 8, false>(cbj + 3 * 8,  fAy, fBy, fAx, fAy, fAz, fBx, fBy, fBz, accA, accB);
        acc_i<2, 8, false>(cbj + 6 * 8,  fAz, fBz, fAx, fAy, fAz, fBx, fBy, fBz, accA, accB);
#pragma unroll
        for (int t = 0; t < 2; ++t) {
            int k = j * 2 + t;
            if (k < 5) { es[PH0_A + k] = accA[t]; es[PH0_B + k] = accB[t]; }
        }
    }
    __syncthreads();

    // window: copy l=2 (+hdr) || compute l=3 (ph0 -> ph1)
    copy_hdr(exf, out, base, rem, tid);
    copy_stage<5, 4, PH0_A>(exf, out, base, rem, tid);
    stage6<5, 2, 2>(scob + OFF3, j, fAx, fAy, fAz, fBx, fBy, fBz,
                    es + PH0_A, es + PH0_B, es + PH1_A, es + PH1_B);
    __syncthreads();

    copy_stage<7, 9, PH1_A>(exf, out, base, rem, tid);
    stage6<7, 4, 4>(scob + OFF4, j, fAx, fAy, fAz, fBx, fBy, fBz,
                    es + PH1_A, es + PH1_B, es + PH0_A, es + PH0_B);
    __syncthreads();

    copy_stage<9, 16, PH0_A>(exf, out, base, rem, tid);
    stage6<9, 4, 4>(scob + OFF5, j, fAx, fAy, fAz, fBx, fBy, fBz,
                    es + PH0_A, es + PH0_B, es + PH1_A, es + PH1_B);
    __syncthreads();

    copy_stage<11, 25, PH1_A>(exf, out, base, rem, tid);
    stage6<11, 4, 4>(scob + OFF6, j, fAx, fAy, fAz, fBx, fBy, fBz,
                     es + PH1_A, es + PH1_B, es + PH0_A, es + PH0_B);
    __syncthreads();

    copy_stage<13, 36, PH0_A>(exf, out, base, rem, tid);
    stage6<13, 4, 4>(scob + OFF7, j, fAx, fAy, fAz, fBx, fBy, fBz,
                     es + PH0_A, es + PH0_B, es + PH1_A, es + PH1_B);
    __syncthreads();

    copy_stage<15, 49, PH1_A>(exf, out, base, rem, tid);
    stage6<15, 6, 8>(scob + OFF8, j, fAx, fAy, fAz, fBx, fBy, fBz,
                     es + PH1_A, es + PH1_B, es + PH0_A, es + PH0_B);
    __syncthreads();

    copy_stage<17, 64, PH0_A>(exf, out, base, rem, tid);
    stage6<17, 6, 8>(scob + OFF9, j, fAx, fAy, fAz, fBx, fBy, fBz,
                     es + PH0_A, es + PH0_B, es + PH1_A, es + PH1_B);
    __syncthreads();

    copy_stage<19, 81, PH1_A>(exf, out, base, rem, tid);
    stage6<19, 6, 8>(scob + OFF10, j, fAx, fAy, fAz, fBx, fBy, fBz,
                     es + PH1_A, es + PH1_B, es + PH0_A, es + PH0_B);
    __syncthreads();

    copy_stage<21, 100, PH0_A>(exf, out, base, rem, tid);
}

extern "C" void kernel_launch(void* const* d_in, const int* in_sizes, int n_in,
                              void* d_out, int out_size) {
    const float* points = (const float*)d_in[0];
    const int N = in_sizes[0] / 3;
    float* out = (float*)d_out;

    cudaFuncSetAttribute(harmonic_kernel,
                         cudaFuncAttributeMaxDynamicSharedMemorySize, SMEM_BYTES);

    const int grid = (N + TILE - 1) / TILE;
    harmonic_kernel<<<grid, BLOCK, SMEM_BYTES>>>(
        points,
        (const float*)d_in[1], (const float*)d_in[2], (const float*)d_in[3],
        (const float*)d_in[4], (const float*)d_in[5], (const float*)d_in[6],
        (const float*)d_in[7], (const float*)d_in[8], (const float*)d_in[9],
        (const float*)d_in[10],
        out, N);
}